// round 7
// baseline (speedup 1.0000x reference)
#include <cuda_runtime.h>
#include <math.h>

// GATLSTMCell: B=2, N=20000, E=320000, IN=64, HID=64, C=256, F=128
constexpr int NN  = 20000;
constexpr int BB  = 2;
constexpr int EE  = 320000;
constexpr int CC  = 256;
constexpr int FD  = 128;
constexpr int HID = 64;

// ---- device scratch ----
__device__ __align__(16) float g_agg[(size_t)BB * NN * FD];
__device__ __align__(16) float g_conv[(size_t)BB * NN * CC];
__device__ float  g_as[BB * NN];
__device__ float  g_ad[BB * NN];
__device__ __align__(16) float g_vs[FD];
__device__ __align__(16) float g_vd[FD];
__device__ int    g_counts[NN];
__device__ int    g_offsets[NN + 1];
__device__ int    g_cursor[NN];
__device__ int    g_csr[EE + NN];
__device__ float2 g_w2[EE + NN];
__device__ int    g_idx64;

// f32x2 packed-FMA helper (Blackwell; ptxas won't emit FFMA2 from C++)
#define FMA2(d_, a_, b_) \
    asm("fma.rn.f32x2 %0, %1, %2, %3;" : "=l"(d_) : "l"(a_), "l"(b_), "l"(d_))
#define UPK2(lo_, hi_, s_) \
    asm("mov.b64 {%0, %1}, %2;" : "=f"(lo_), "=f"(hi_) : "l"(s_))

__device__ __forceinline__ float leaky(float e) {
    return (e >= 0.f) ? e : 0.2f * e;
}

// ---------------------------------------------------------------------------
// blocks 0..78: zero counts; block 79: v = W^T att; block 80: idx dtype detect
__global__ void __launch_bounds__(256) initvs_k(const float* __restrict__ W,
                                                const float* __restrict__ att_s,
                                                const float* __restrict__ att_d,
                                                const int* __restrict__ e,
                                                int nwords) {
    int t = threadIdx.x;
    if (blockIdx.x < 79) {
        int i = blockIdx.x * 256 + t;
        if (i < NN) g_counts[i] = 0;
        return;
    }
    if (blockIdx.x == 80) {
        if (t < 32) {
            int lim = nwords < 512 ? nwords : 512;
            int any = 0;
            for (int i = 1 + 2 * t; i < lim; i += 64) any |= e[i];
            any = __reduce_or_sync(0xffffffffu, any);
            if (t == 0) g_idx64 = (any == 0) ? 1 : 0;
        }
        return;
    }
    __shared__ float sv[128], sd[128];
    int f  = t & 127;
    int hc = t >> 7;
    float s = 0.f, d = 0.f;
    for (int c = hc * 128; c < hc * 128 + 128; c++) {
        float w = W[(size_t)c * FD + f];
        s = fmaf(att_s[c], w, s);
        d = fmaf(att_d[c], w, d);
    }
    if (hc == 0) { sv[f] = s; sd[f] = d; }
    __syncthreads();
    if (hc == 1) { g_vs[f] = sv[f] + s; g_vd[f] = sd[f] + d; }
}

// a_s[b,n] = x . v_s.  Warp per (b,n); lanes 0-15 read inp float4, 16-31 hcur.
__global__ void __launch_bounds__(256) asd_k(const float* __restrict__ inp,
                                             const float* __restrict__ hcur) {
    int wid  = (blockIdx.x * blockDim.x + threadIdx.x) >> 5;
    int lane = threadIdx.x & 31;
    if (wid >= BB * NN) return;
    const float* basep = (lane & 16) ? hcur : inp;
    int f0 = (lane & 16) * 4 + (lane & 15) * 4;
    float4 v  = *reinterpret_cast<const float4*>(basep + (size_t)wid * 64 + (lane & 15) * 4);
    float4 vs = *reinterpret_cast<const float4*>(g_vs + f0);
    float4 vd = *reinterpret_cast<const float4*>(g_vd + f0);
    float s = v.x * vs.x + v.y * vs.y + v.z * vs.z + v.w * vs.w;
    float d = v.x * vd.x + v.y * vd.y + v.z * vd.z + v.w * vd.w;
    #pragma unroll
    for (int o = 16; o > 0; o >>= 1) {
        s += __shfl_down_sync(0xffffffffu, s, o);
        d += __shfl_down_sync(0xffffffffu, d, o);
    }
    if (lane == 0) { g_as[wid] = s; g_ad[wid] = d; }
}

// ---------------------------------------------------------------------------
__device__ __forceinline__ int load_index(const void* p, int i, int is64) {
    return is64 ? (int)((const long long*)p)[i] : ((const int*)p)[i];
}

__global__ void hist_k(const void* __restrict__ edges, int E) {
    int i = blockIdx.x * blockDim.x + threadIdx.x;
    if (i >= E) return;
    int d = load_index(edges, E + i, g_idx64);
    if ((unsigned)d < (unsigned)NN) atomicAdd(&g_counts[d], 1);
}

// Single-block exclusive scan of (counts+1): 1024 threads x 20 items each.
__global__ void __launch_bounds__(1024) scan_k() {
    __shared__ int wsums[32];
    int t = threadIdx.x, lane = t & 31, w = t >> 5;
    int base = t * 20;
    int c[20];
    int sum = 0;
    #pragma unroll
    for (int q = 0; q < 20; q++) {
        int idx = base + q;
        int v = (idx < NN) ? (g_counts[idx] + 1) : 0;
        c[q] = sum;
        sum += v;
    }
    int incl = sum;
    #pragma unroll
    for (int o = 1; o < 32; o <<= 1) {
        int x = __shfl_up_sync(0xffffffffu, incl, o);
        if (lane >= o) incl += x;
    }
    int wex = incl - sum;
    if (lane == 31) wsums[w] = incl;
    __syncthreads();
    if (w == 0) {
        int v2 = wsums[lane];
        int incl2 = v2;
        #pragma unroll
        for (int o = 1; o < 32; o <<= 1) {
            int x = __shfl_up_sync(0xffffffffu, incl2, o);
            if (lane >= o) incl2 += x;
        }
        wsums[lane] = incl2 - v2;
    }
    __syncthreads();
    int off = wsums[w] + wex;
    #pragma unroll
    for (int q = 0; q < 20; q++) {
        int idx = base + q;
        if (idx < NN) {
            int o = off + c[q];
            g_offsets[idx] = o;
            g_cursor[idx]  = o;
            if (idx == NN - 1) {
                int next = (q == 19) ? sum : c[q + 1];
                g_offsets[NN] = off + next;
            }
        }
    }
}

// Scatter CSR AND precompute softmax numerators for both batches per slot.
__global__ void fill_k(const void* __restrict__ edges, int E) {
    int i = blockIdx.x * blockDim.x + threadIdx.x;
    if (i >= E) return;
    int is64 = g_idx64;
    int s = load_index(edges, i, is64);
    int d = load_index(edges, E + i, is64);
    if ((unsigned)d < (unsigned)NN && (unsigned)s < (unsigned)NN) {
        int pos = atomicAdd(&g_cursor[d], 1);
        g_csr[pos] = s;
        float w0 = __expf(leaky(g_as[s] + g_ad[d]));
        float w1 = __expf(leaky(g_as[NN + s] + g_ad[NN + d]));
        g_w2[pos] = make_float2(w0, w1);
    }
}

// ---------------------------------------------------------------------------
// agg[b,n,:] = (1/S) sum_e w_e * x[src,:].  ONE warp per dst, BOTH batches:
// lanes 0-15 batch 0, 16-31 batch 1; each lane covers 8 features (2 LDG.128).
__global__ void __launch_bounds__(256) agg_k(const float* __restrict__ inp,
                                             const float* __restrict__ hcur) {
    int n    = (blockIdx.x * blockDim.x + threadIdx.x) >> 5;
    int lane = threadIdx.x & 31;
    if (n >= NN) return;
    int b  = lane >> 4;
    int fl = lane & 15;

    int off0 = g_offsets[n];
    int last = g_offsets[n + 1] - 1;        // last slot = self loop (reserved)

    const float* basep = ((fl & 8) ? hcur : inp) + (size_t)b * NN * 64 + (fl & 7) * 8;

    float4 acc0 = make_float4(0.f, 0.f, 0.f, 0.f);
    float4 acc1 = make_float4(0.f, 0.f, 0.f, 0.f);
    float S = 0.f;

    int i = off0;
    for (; i + 1 < last; i += 2) {
        int s0 = g_csr[i];
        int s1 = g_csr[i + 1];
        float2 w20 = g_w2[i];
        float2 w21 = g_w2[i + 1];
        const float* r0 = basep + (size_t)s0 * 64;
        const float* r1 = basep + (size_t)s1 * 64;
        float4 v00 = *reinterpret_cast<const float4*>(r0);
        float4 v01 = *reinterpret_cast<const float4*>(r0 + 4);
        float4 v10 = *reinterpret_cast<const float4*>(r1);
        float4 v11 = *reinterpret_cast<const float4*>(r1 + 4);
        float wa = b ? w20.y : w20.x;
        float wb = b ? w21.y : w21.x;
        S += wa + wb;
        acc0.x = fmaf(wa, v00.x, acc0.x); acc0.y = fmaf(wa, v00.y, acc0.y);
        acc0.z = fmaf(wa, v00.z, acc0.z); acc0.w = fmaf(wa, v00.w, acc0.w);
        acc1.x = fmaf(wa, v01.x, acc1.x); acc1.y = fmaf(wa, v01.y, acc1.y);
        acc1.z = fmaf(wa, v01.z, acc1.z); acc1.w = fmaf(wa, v01.w, acc1.w);
        acc0.x = fmaf(wb, v10.x, acc0.x); acc0.y = fmaf(wb, v10.y, acc0.y);
        acc0.z = fmaf(wb, v10.z, acc0.z); acc0.w = fmaf(wb, v10.w, acc0.w);
        acc1.x = fmaf(wb, v11.x, acc1.x); acc1.y = fmaf(wb, v11.y, acc1.y);
        acc1.z = fmaf(wb, v11.z, acc1.z); acc1.w = fmaf(wb, v11.w, acc1.w);
    }
    if (i < last) {
        int s0 = g_csr[i];
        float2 w20 = g_w2[i];
        const float* r0 = basep + (size_t)s0 * 64;
        float4 v00 = *reinterpret_cast<const float4*>(r0);
        float4 v01 = *reinterpret_cast<const float4*>(r0 + 4);
        float wa = b ? w20.y : w20.x;
        S += wa;
        acc0.x = fmaf(wa, v00.x, acc0.x); acc0.y = fmaf(wa, v00.y, acc0.y);
        acc0.z = fmaf(wa, v00.z, acc0.z); acc0.w = fmaf(wa, v00.w, acc0.w);
        acc1.x = fmaf(wa, v01.x, acc1.x); acc1.y = fmaf(wa, v01.y, acc1.y);
        acc1.z = fmaf(wa, v01.z, acc1.z); acc1.w = fmaf(wa, v01.w, acc1.w);
    }
    // self loop
    {
        float w = __expf(leaky(g_as[b * NN + n] + g_ad[b * NN + n]));
        const float* rs = basep + (size_t)n * 64;
        float4 v0 = *reinterpret_cast<const float4*>(rs);
        float4 v1 = *reinterpret_cast<const float4*>(rs + 4);
        S += w;
        acc0.x = fmaf(w, v0.x, acc0.x); acc0.y = fmaf(w, v0.y, acc0.y);
        acc0.z = fmaf(w, v0.z, acc0.z); acc0.w = fmaf(w, v0.w, acc0.w);
        acc1.x = fmaf(w, v1.x, acc1.x); acc1.y = fmaf(w, v1.y, acc1.y);
        acc1.z = fmaf(w, v1.z, acc1.z); acc1.w = fmaf(w, v1.w, acc1.w);
    }
    float inv = 1.0f / S;
    float* o = g_agg + ((size_t)(b * NN + n)) * FD + fl * 8;
    *reinterpret_cast<float4*>(o) =
        make_float4(acc0.x * inv, acc0.y * inv, acc0.z * inv, acc0.w * inv);
    *reinterpret_cast<float4*>(o + 4) =
        make_float4(acc1.x * inv, acc1.y * inv, acc1.z * inv, acc1.w * inv);
}

// ---------------------------------------------------------------------------
// conv[b,n,c] = sum_f agg[b,n,f] * W[c,f].  128x128 tile, 8x8 micro-tile.
// Row-pair accumulators (ulonglong2 LDS, zero movs) x duplicated-B smem
// ((b_j,b_j) pairs straight from LDS.128).  K-chunk 16, 25.3 KB smem.
__global__ void __launch_bounds__(256, 2) gemm_k(const float* __restrict__ W) {
    __shared__ float As[16][132];
    __shared__ float Bs[16][264];

    const int t  = threadIdx.x;
    const int b  = blockIdx.z;
    const int n0 = blockIdx.x * 128;
    const int c0 = blockIdx.y * 128;
    const int tx = t & 15;
    const int ty = t >> 4;

    unsigned long long acc2[4][8];
    #pragma unroll
    for (int p = 0; p < 4; p++)
        #pragma unroll
        for (int j = 0; j < 8; j++) acc2[p][j] = 0ull;

    #pragma unroll
    for (int kc = 0; kc < 8; kc++) {
        // A tile: 128 rows x 16 k  (512 float4, 2 passes)
        #pragma unroll
        for (int pass = 0; pass < 2; pass++) {
            int idx = pass * 256 + t;
            int k   = (idx & 3) * 4;
            int row = idx >> 2;
            float4 v = make_float4(0.f, 0.f, 0.f, 0.f);
            int node = n0 + row;
            if (node < NN)
                v = *reinterpret_cast<const float4*>(
                        g_agg + ((size_t)(b * NN + node)) * FD + kc * 16 + k);
            As[k + 0][row] = v.x; As[k + 1][row] = v.y;
            As[k + 2][row] = v.z; As[k + 3][row] = v.w;
        }
        // B tile duplicated: Bs[k][2r] = Bs[k][2r+1] = W[c0+r][kc*16+k]
        #pragma unroll
        for (int pass = 0; pass < 2; pass++) {
            int idx = pass * 256 + t;
            int k   = (idx & 3) * 4;
            int row = idx >> 2;
            float4 v = *reinterpret_cast<const float4*>(
                           W + (size_t)(c0 + row) * FD + kc * 16 + k);
            Bs[k + 0][2 * row] = v.x; Bs[k + 0][2 * row + 1] = v.x;
            Bs[k + 1][2 * row] = v.y; Bs[k + 1][2 * row + 1] = v.y;
            Bs[k + 2][2 * row] = v.z; Bs[k + 2][2 * row + 1] = v.z;
            Bs[k + 3][2 * row] = v.w; Bs[k + 3][2 * row + 1] = v.w;
        }
        __syncthreads();

        #pragma unroll
        for (int k = 0; k < 16; k++) {
            ulonglong2 a01 = *reinterpret_cast<const ulonglong2*>(&As[k][ty * 8]);
            ulonglong2 a23 = *reinterpret_cast<const ulonglong2*>(&As[k][ty * 8 + 4]);
            ulonglong2 b01 = *reinterpret_cast<const ulonglong2*>(&Bs[k][tx * 16]);
            ulonglong2 b23 = *reinterpret_cast<const ulonglong2*>(&Bs[k][tx * 16 + 4]);
            ulonglong2 b45 = *reinterpret_cast<const ulonglong2*>(&Bs[k][tx * 16 + 8]);
            ulonglong2 b67 = *reinterpret_cast<const ulonglong2*>(&Bs[k][tx * 16 + 12]);
            unsigned long long ap[4] = {a01.x, a01.y, a23.x, a23.y};
            unsigned long long bd[8] = {b01.x, b01.y, b23.x, b23.y,
                                        b45.x, b45.y, b67.x, b67.y};
            #pragma unroll
            for (int p = 0; p < 4; p++) {
                FMA2(acc2[p][0], ap[p], bd[0]);
                FMA2(acc2[p][1], ap[p], bd[1]);
                FMA2(acc2[p][2], ap[p], bd[2]);
                FMA2(acc2[p][3], ap[p], bd[3]);
                FMA2(acc2[p][4], ap[p], bd[4]);
                FMA2(acc2[p][5], ap[p], bd[5]);
                FMA2(acc2[p][6], ap[p], bd[6]);
                FMA2(acc2[p][7], ap[p], bd[7]);
            }
        }
        __syncthreads();
    }

    #pragma unroll
    for (int p = 0; p < 4; p++) {
        float rlo[8], rhi[8];
        #pragma unroll
        for (int j = 0; j < 8; j++) UPK2(rlo[j], rhi[j], acc2[p][j]);
        int n_a = n0 + ty * 8 + 2 * p;
        if (n_a < NN) {
            float* dst = g_conv + ((size_t)(b * NN + n_a)) * CC + c0 + tx * 8;
            *reinterpret_cast<float4*>(dst)     = make_float4(rlo[0], rlo[1], rlo[2], rlo[3]);
            *reinterpret_cast<float4*>(dst + 4) = make_float4(rlo[4], rlo[5], rlo[6], rlo[7]);
        }
        int n_b = n_a + 1;
        if (n_b < NN) {
            float* dst = g_conv + ((size_t)(b * NN + n_b)) * CC + c0 + tx * 8;
            *reinterpret_cast<float4*>(dst)     = make_float4(rhi[0], rhi[1], rhi[2], rhi[3]);
            *reinterpret_cast<float4*>(dst + 4) = make_float4(rhi[4], rhi[5], rhi[6], rhi[7]);
        }
    }
}

// ---------------------------------------------------------------------------
// LSTM epilogue: thread per (b,n, 4 channels)  — all float4.
__global__ void __launch_bounds__(256) lstm_k(const float* __restrict__ bias,
                                              const float* __restrict__ c_cur,
                                              float* __restrict__ out) {
    int gid = blockIdx.x * blockDim.x + threadIdx.x;
    if (gid >= BB * NN * 16) return;
    int bn = gid >> 4;
    int j0 = (gid & 15) * 4;
    const float* cv = g_conv + (size_t)bn * CC;
    float4 xi = *reinterpret_cast<const float4*>(cv + j0);
    float4 xf = *reinterpret_cast<const float4*>(cv + 64 + j0);
    float4 xo = *reinterpret_cast<const float4*>(cv + 128 + j0);
    float4 xg = *reinterpret_cast<const float4*>(cv + 192 + j0);
    float4 bi = *reinterpret_cast<const float4*>(bias + j0);
    float4 bf = *reinterpret_cast<const float4*>(bias + 64 + j0);
    float4 bo = *reinterpret_cast<const float4*>(bias + 128 + j0);
    float4 bg = *reinterpret_cast<const float4*>(bias + 192 + j0);
    float4 cp = *reinterpret_cast<const float4*>(c_cur + (size_t)bn * HID + j0);

    float4 hn, cn;
    {
        float iv = 1.f / (1.f + __expf(-(xi.x + bi.x)));
        float fv = 1.f / (1.f + __expf(-(xf.x + bf.x)));
        float ov = 1.f / (1.f + __expf(-(xo.x + bo.x)));
        float gv = tanhf(xg.x + bg.x);
        cn.x = fmaf(fv, cp.x, iv * gv); hn.x = ov * tanhf(cn.x);
    }
    {
        float iv = 1.f / (1.f + __expf(-(xi.y + bi.y)));
        float fv = 1.f / (1.f + __expf(-(xf.y + bf.y)));
        float ov = 1.f / (1.f + __expf(-(xo.y + bo.y)));
        float gv = tanhf(xg.y + bg.y);
        cn.y = fmaf(fv, cp.y, iv * gv); hn.y = ov * tanhf(cn.y);
    }
    {
        float iv = 1.f / (1.f + __expf(-(xi.z + bi.z)));
        float fv = 1.f / (1.f + __expf(-(xf.z + bf.z)));
        float ov = 1.f / (1.f + __expf(-(xo.z + bo.z)));
        float gv = tanhf(xg.z + bg.z);
        cn.z = fmaf(fv, cp.z, iv * gv); hn.z = ov * tanhf(cn.z);
    }
    {
        float iv = 1.f / (1.f + __expf(-(xi.w + bi.w)));
        float fv = 1.f / (1.f + __expf(-(xf.w + bf.w)));
        float ov = 1.f / (1.f + __expf(-(xo.w + bo.w)));
        float gv = tanhf(xg.w + bg.w);
        cn.w = fmaf(fv, cp.w, iv * gv); hn.w = ov * tanhf(cn.w);
    }
    *reinterpret_cast<float4*>(out + (size_t)bn * HID + j0) = hn;
    *reinterpret_cast<float4*>(out + (size_t)BB * NN * HID + (size_t)bn * HID + j0) = cn;
}

// ---------------------------------------------------------------------------
extern "C" void kernel_launch(void* const* d_in, const int* in_sizes, int n_in,
                              void* d_out, int out_size) {
    const float* inp   = (const float*)d_in[0];
    const float* hcur  = (const float*)d_in[1];
    const float* ccur  = (const float*)d_in[2];
    const float* W     = (const float*)d_in[3];
    const float* att_s = (const float*)d_in[4];
    const float* att_d = (const float*)d_in[5];
    const float* bias  = (const float*)d_in[6];
    const void*  edges = d_in[7];
    float* out = (float*)d_out;

    int E = in_sizes[7] / 2;

    initvs_k<<<81, 256>>>(W, att_s, att_d, (const int*)edges, in_sizes[7]);
    asd_k<<<(BB * NN * 32 + 255) / 256, 256>>>(inp, hcur);
    hist_k<<<(E + 255) / 256, 256>>>(edges, E);
    scan_k<<<1, 1024>>>();
    fill_k<<<(E + 255) / 256, 256>>>(edges, E);
    agg_k<<<(NN * 32 + 255) / 256, 256>>>(inp, hcur);
    gemm_k<<<dim3((NN + 127) / 128, CC / 128, BB), 256>>>(W);
    lstm_k<<<(BB * NN * 16 + 255) / 256, 256>>>(bias, ccur, out);
}

// round 8
// speedup vs baseline: 1.0002x; 1.0002x over previous
#include <cuda_runtime.h>
#include <math.h>

// GATLSTMCell: B=2, N=20000, E=320000, IN=64, HID=64, C=256, F=128
constexpr int NN  = 20000;
constexpr int BB  = 2;
constexpr int EE  = 320000;
constexpr int CC  = 256;
constexpr int FD  = 128;
constexpr int HID = 64;

// ---- device scratch ----
__device__ __align__(16) float g_agg[(size_t)BB * NN * FD];
__device__ __align__(16) float g_conv[(size_t)BB * NN * CC];
__device__ float  g_as[BB * NN];
__device__ float  g_ad[BB * NN];
__device__ __align__(16) float g_vs[FD];
__device__ __align__(16) float g_vd[FD];
__device__ int    g_counts[NN];
__device__ int    g_offsets[NN + 1];
__device__ int    g_cursor[NN];
__device__ int    g_csr[EE + NN];
__device__ float2 g_w2[EE + NN];
__device__ int    g_idx64;

// f32x2 packed-FMA helper (Blackwell; ptxas won't emit FFMA2 from C++)
#define FMA2(d_, a_, b_) \
    asm("fma.rn.f32x2 %0, %1, %2, %3;" : "=l"(d_) : "l"(a_), "l"(b_), "l"(d_))
#define UPK2(lo_, hi_, s_) \
    asm("mov.b64 {%0, %1}, %2;" : "=f"(lo_), "=f"(hi_) : "l"(s_))

__device__ __forceinline__ float leaky(float e) {
    return (e >= 0.f) ? e : 0.2f * e;
}

// ---------------------------------------------------------------------------
// blocks 0..78: zero counts; block 79: v = W^T att; block 80: idx dtype detect
__global__ void __launch_bounds__(256) initvs_k(const float* __restrict__ W,
                                                const float* __restrict__ att_s,
                                                const float* __restrict__ att_d,
                                                const int* __restrict__ e,
                                                int nwords) {
    int t = threadIdx.x;
    if (blockIdx.x < 79) {
        int i = blockIdx.x * 256 + t;
        if (i < NN) g_counts[i] = 0;
        return;
    }
    if (blockIdx.x == 80) {
        if (t < 32) {
            int lim = nwords < 512 ? nwords : 512;
            int any = 0;
            for (int i = 1 + 2 * t; i < lim; i += 64) any |= e[i];
            any = __reduce_or_sync(0xffffffffu, any);
            if (t == 0) g_idx64 = (any == 0) ? 1 : 0;
        }
        return;
    }
    __shared__ float sv[128], sd[128];
    int f  = t & 127;
    int hc = t >> 7;
    float s = 0.f, d = 0.f;
    for (int c = hc * 128; c < hc * 128 + 128; c++) {
        float w = W[(size_t)c * FD + f];
        s = fmaf(att_s[c], w, s);
        d = fmaf(att_d[c], w, d);
    }
    if (hc == 0) { sv[f] = s; sd[f] = d; }
    __syncthreads();
    if (hc == 1) { g_vs[f] = sv[f] + s; g_vd[f] = sd[f] + d; }
}

// a_s[b,n] = x . v_s.  Warp per (b,n); lanes 0-15 read inp float4, 16-31 hcur.
__global__ void __launch_bounds__(256) asd_k(const float* __restrict__ inp,
                                             const float* __restrict__ hcur) {
    int wid  = (blockIdx.x * blockDim.x + threadIdx.x) >> 5;
    int lane = threadIdx.x & 31;
    if (wid >= BB * NN) return;
    const float* basep = (lane & 16) ? hcur : inp;
    int f0 = (lane & 16) * 4 + (lane & 15) * 4;
    float4 v  = *reinterpret_cast<const float4*>(basep + (size_t)wid * 64 + (lane & 15) * 4);
    float4 vs = *reinterpret_cast<const float4*>(g_vs + f0);
    float4 vd = *reinterpret_cast<const float4*>(g_vd + f0);
    float s = v.x * vs.x + v.y * vs.y + v.z * vs.z + v.w * vs.w;
    float d = v.x * vd.x + v.y * vd.y + v.z * vd.z + v.w * vd.w;
    #pragma unroll
    for (int o = 16; o > 0; o >>= 1) {
        s += __shfl_down_sync(0xffffffffu, s, o);
        d += __shfl_down_sync(0xffffffffu, d, o);
    }
    if (lane == 0) { g_as[wid] = s; g_ad[wid] = d; }
}

// ---------------------------------------------------------------------------
__device__ __forceinline__ int load_index(const void* p, int i, int is64) {
    return is64 ? (int)((const long long*)p)[i] : ((const int*)p)[i];
}

__global__ void hist_k(const void* __restrict__ edges, int E) {
    int i = blockIdx.x * blockDim.x + threadIdx.x;
    if (i >= E) return;
    int d = load_index(edges, E + i, g_idx64);
    if ((unsigned)d < (unsigned)NN) atomicAdd(&g_counts[d], 1);
}

// Single-block exclusive scan of (counts+1): 1024 threads x 20 items each.
__global__ void __launch_bounds__(1024) scan_k() {
    __shared__ int wsums[32];
    int t = threadIdx.x, lane = t & 31, w = t >> 5;
    int base = t * 20;
    int c[20];
    int sum = 0;
    #pragma unroll
    for (int q = 0; q < 20; q++) {
        int idx = base + q;
        int v = (idx < NN) ? (g_counts[idx] + 1) : 0;
        c[q] = sum;
        sum += v;
    }
    int incl = sum;
    #pragma unroll
    for (int o = 1; o < 32; o <<= 1) {
        int x = __shfl_up_sync(0xffffffffu, incl, o);
        if (lane >= o) incl += x;
    }
    int wex = incl - sum;
    if (lane == 31) wsums[w] = incl;
    __syncthreads();
    if (w == 0) {
        int v2 = wsums[lane];
        int incl2 = v2;
        #pragma unroll
        for (int o = 1; o < 32; o <<= 1) {
            int x = __shfl_up_sync(0xffffffffu, incl2, o);
            if (lane >= o) incl2 += x;
        }
        wsums[lane] = incl2 - v2;
    }
    __syncthreads();
    int off = wsums[w] + wex;
    #pragma unroll
    for (int q = 0; q < 20; q++) {
        int idx = base + q;
        if (idx < NN) {
            int o = off + c[q];
            g_offsets[idx] = o;
            g_cursor[idx]  = o;
            if (idx == NN - 1) {
                int next = (q == 19) ? sum : c[q + 1];
                g_offsets[NN] = off + next;
            }
        }
    }
}

// Scatter CSR AND precompute softmax numerators for both batches per slot.
__global__ void fill_k(const void* __restrict__ edges, int E) {
    int i = blockIdx.x * blockDim.x + threadIdx.x;
    if (i >= E) return;
    int is64 = g_idx64;
    int s = load_index(edges, i, is64);
    int d = load_index(edges, E + i, is64);
    if ((unsigned)d < (unsigned)NN && (unsigned)s < (unsigned)NN) {
        int pos = atomicAdd(&g_cursor[d], 1);
        g_csr[pos] = s;
        float w0 = __expf(leaky(g_as[s] + g_ad[d]));
        float w1 = __expf(leaky(g_as[NN + s] + g_ad[NN + d]));
        g_w2[pos] = make_float2(w0, w1);
    }
}

// ---------------------------------------------------------------------------
// agg[b,n,:] = (1/S) sum_e w_e * x[src,:].  ONE warp per dst, BOTH batches:
// lanes 0-15 batch 0, 16-31 batch 1; each lane covers 8 features (2 LDG.128).
__global__ void __launch_bounds__(256) agg_k(const float* __restrict__ inp,
                                             const float* __restrict__ hcur) {
    int n    = (blockIdx.x * blockDim.x + threadIdx.x) >> 5;
    int lane = threadIdx.x & 31;
    if (n >= NN) return;
    int b  = lane >> 4;
    int fl = lane & 15;

    int off0 = g_offsets[n];
    int last = g_offsets[n + 1] - 1;        // last slot = self loop (reserved)

    const float* basep = ((fl & 8) ? hcur : inp) + (size_t)b * NN * 64 + (fl & 7) * 8;

    float4 acc0 = make_float4(0.f, 0.f, 0.f, 0.f);
    float4 acc1 = make_float4(0.f, 0.f, 0.f, 0.f);
    float S = 0.f;

    int i = off0;
    for (; i + 1 < last; i += 2) {
        int s0 = g_csr[i];
        int s1 = g_csr[i + 1];
        float2 w20 = g_w2[i];
        float2 w21 = g_w2[i + 1];
        const float* r0 = basep + (size_t)s0 * 64;
        const float* r1 = basep + (size_t)s1 * 64;
        float4 v00 = *reinterpret_cast<const float4*>(r0);
        float4 v01 = *reinterpret_cast<const float4*>(r0 + 4);
        float4 v10 = *reinterpret_cast<const float4*>(r1);
        float4 v11 = *reinterpret_cast<const float4*>(r1 + 4);
        float wa = b ? w20.y : w20.x;
        float wb = b ? w21.y : w21.x;
        S += wa + wb;
        acc0.x = fmaf(wa, v00.x, acc0.x); acc0.y = fmaf(wa, v00.y, acc0.y);
        acc0.z = fmaf(wa, v00.z, acc0.z); acc0.w = fmaf(wa, v00.w, acc0.w);
        acc1.x = fmaf(wa, v01.x, acc1.x); acc1.y = fmaf(wa, v01.y, acc1.y);
        acc1.z = fmaf(wa, v01.z, acc1.z); acc1.w = fmaf(wa, v01.w, acc1.w);
        acc0.x = fmaf(wb, v10.x, acc0.x); acc0.y = fmaf(wb, v10.y, acc0.y);
        acc0.z = fmaf(wb, v10.z, acc0.z); acc0.w = fmaf(wb, v10.w, acc0.w);
        acc1.x = fmaf(wb, v11.x, acc1.x); acc1.y = fmaf(wb, v11.y, acc1.y);
        acc1.z = fmaf(wb, v11.z, acc1.z); acc1.w = fmaf(wb, v11.w, acc1.w);
    }
    if (i < last) {
        int s0 = g_csr[i];
        float2 w20 = g_w2[i];
        const float* r0 = basep + (size_t)s0 * 64;
        float4 v00 = *reinterpret_cast<const float4*>(r0);
        float4 v01 = *reinterpret_cast<const float4*>(r0 + 4);
        float wa = b ? w20.y : w20.x;
        S += wa;
        acc0.x = fmaf(wa, v00.x, acc0.x); acc0.y = fmaf(wa, v00.y, acc0.y);
        acc0.z = fmaf(wa, v00.z, acc0.z); acc0.w = fmaf(wa, v00.w, acc0.w);
        acc1.x = fmaf(wa, v01.x, acc1.x); acc1.y = fmaf(wa, v01.y, acc1.y);
        acc1.z = fmaf(wa, v01.z, acc1.z); acc1.w = fmaf(wa, v01.w, acc1.w);
    }
    // self loop
    {
        float w = __expf(leaky(g_as[b * NN + n] + g_ad[b * NN + n]));
        const float* rs = basep + (size_t)n * 64;
        float4 v0 = *reinterpret_cast<const float4*>(rs);
        float4 v1 = *reinterpret_cast<const float4*>(rs + 4);
        S += w;
        acc0.x = fmaf(w, v0.x, acc0.x); acc0.y = fmaf(w, v0.y, acc0.y);
        acc0.z = fmaf(w, v0.z, acc0.z); acc0.w = fmaf(w, v0.w, acc0.w);
        acc1.x = fmaf(w, v1.x, acc1.x); acc1.y = fmaf(w, v1.y, acc1.y);
        acc1.z = fmaf(w, v1.z, acc1.z); acc1.w = fmaf(w, v1.w, acc1.w);
    }
    float inv = 1.0f / S;
    float* o = g_agg + ((size_t)(b * NN + n)) * FD + fl * 8;
    *reinterpret_cast<float4*>(o) =
        make_float4(acc0.x * inv, acc0.y * inv, acc0.z * inv, acc0.w * inv);
    *reinterpret_cast<float4*>(o + 4) =
        make_float4(acc1.x * inv, acc1.y * inv, acc1.z * inv, acc1.w * inv);
}

// ---------------------------------------------------------------------------
// conv[b,n,c] = sum_f agg[b,n,f] * W[c,f].  128x128 tile, 8x8 micro-tile.
// Row-pair accumulators (ulonglong2 LDS, zero movs) x duplicated-B smem
// ((b_j,b_j) pairs straight from LDS.128).  K-chunk 16, 25.3 KB smem.
__global__ void __launch_bounds__(256, 2) gemm_k(const float* __restrict__ W) {
    __shared__ float As[16][132];
    __shared__ float Bs[16][264];

    const int t  = threadIdx.x;
    const int b  = blockIdx.z;
    const int n0 = blockIdx.x * 128;
    const int c0 = blockIdx.y * 128;
    const int tx = t & 15;
    const int ty = t >> 4;

    unsigned long long acc2[4][8];
    #pragma unroll
    for (int p = 0; p < 4; p++)
        #pragma unroll
        for (int j = 0; j < 8; j++) acc2[p][j] = 0ull;

    #pragma unroll
    for (int kc = 0; kc < 8; kc++) {
        // A tile: 128 rows x 16 k  (512 float4, 2 passes)
        #pragma unroll
        for (int pass = 0; pass < 2; pass++) {
            int idx = pass * 256 + t;
            int k   = (idx & 3) * 4;
            int row = idx >> 2;
            float4 v = make_float4(0.f, 0.f, 0.f, 0.f);
            int node = n0 + row;
            if (node < NN)
                v = *reinterpret_cast<const float4*>(
                        g_agg + ((size_t)(b * NN + node)) * FD + kc * 16 + k);
            As[k + 0][row] = v.x; As[k + 1][row] = v.y;
            As[k + 2][row] = v.z; As[k + 3][row] = v.w;
        }
        // B tile duplicated: Bs[k][2r] = Bs[k][2r+1] = W[c0+r][kc*16+k]
        #pragma unroll
        for (int pass = 0; pass < 2; pass++) {
            int idx = pass * 256 + t;
            int k   = (idx & 3) * 4;
            int row = idx >> 2;
            float4 v = *reinterpret_cast<const float4*>(
                           W + (size_t)(c0 + row) * FD + kc * 16 + k);
            Bs[k + 0][2 * row] = v.x; Bs[k + 0][2 * row + 1] = v.x;
            Bs[k + 1][2 * row] = v.y; Bs[k + 1][2 * row + 1] = v.y;
            Bs[k + 2][2 * row] = v.z; Bs[k + 2][2 * row + 1] = v.z;
            Bs[k + 3][2 * row] = v.w; Bs[k + 3][2 * row + 1] = v.w;
        }
        __syncthreads();

        #pragma unroll
        for (int k = 0; k < 16; k++) {
            ulonglong2 a01 = *reinterpret_cast<const ulonglong2*>(&As[k][ty * 8]);
            ulonglong2 a23 = *reinterpret_cast<const ulonglong2*>(&As[k][ty * 8 + 4]);
            ulonglong2 b01 = *reinterpret_cast<const ulonglong2*>(&Bs[k][tx * 16]);
            ulonglong2 b23 = *reinterpret_cast<const ulonglong2*>(&Bs[k][tx * 16 + 4]);
            ulonglong2 b45 = *reinterpret_cast<const ulonglong2*>(&Bs[k][tx * 16 + 8]);
            ulonglong2 b67 = *reinterpret_cast<const ulonglong2*>(&Bs[k][tx * 16 + 12]);
            unsigned long long ap[4] = {a01.x, a01.y, a23.x, a23.y};
            unsigned long long bd[8] = {b01.x, b01.y, b23.x, b23.y,
                                        b45.x, b45.y, b67.x, b67.y};
            #pragma unroll
            for (int p = 0; p < 4; p++) {
                FMA2(acc2[p][0], ap[p], bd[0]);
                FMA2(acc2[p][1], ap[p], bd[1]);
                FMA2(acc2[p][2], ap[p], bd[2]);
                FMA2(acc2[p][3], ap[p], bd[3]);
                FMA2(acc2[p][4], ap[p], bd[4]);
                FMA2(acc2[p][5], ap[p], bd[5]);
                FMA2(acc2[p][6], ap[p], bd[6]);
                FMA2(acc2[p][7], ap[p], bd[7]);
            }
        }
        __syncthreads();
    }

    #pragma unroll
    for (int p = 0; p < 4; p++) {
        float rlo[8], rhi[8];
        #pragma unroll
        for (int j = 0; j < 8; j++) UPK2(rlo[j], rhi[j], acc2[p][j]);
        int n_a = n0 + ty * 8 + 2 * p;
        if (n_a < NN) {
            float* dst = g_conv + ((size_t)(b * NN + n_a)) * CC + c0 + tx * 8;
            *reinterpret_cast<float4*>(dst)     = make_float4(rlo[0], rlo[1], rlo[2], rlo[3]);
            *reinterpret_cast<float4*>(dst + 4) = make_float4(rlo[4], rlo[5], rlo[6], rlo[7]);
        }
        int n_b = n_a + 1;
        if (n_b < NN) {
            float* dst = g_conv + ((size_t)(b * NN + n_b)) * CC + c0 + tx * 8;
            *reinterpret_cast<float4*>(dst)     = make_float4(rhi[0], rhi[1], rhi[2], rhi[3]);
            *reinterpret_cast<float4*>(dst + 4) = make_float4(rhi[4], rhi[5], rhi[6], rhi[7]);
        }
    }
}

// ---------------------------------------------------------------------------
// LSTM epilogue: thread per (b,n, 4 channels)  — all float4.
__global__ void __launch_bounds__(256) lstm_k(const float* __restrict__ bias,
                                              const float* __restrict__ c_cur,
                                              float* __restrict__ out) {
    int gid = blockIdx.x * blockDim.x + threadIdx.x;
    if (gid >= BB * NN * 16) return;
    int bn = gid >> 4;
    int j0 = (gid & 15) * 4;
    const float* cv = g_conv + (size_t)bn * CC;
    float4 xi = *reinterpret_cast<const float4*>(cv + j0);
    float4 xf = *reinterpret_cast<const float4*>(cv + 64 + j0);
    float4 xo = *reinterpret_cast<const float4*>(cv + 128 + j0);
    float4 xg = *reinterpret_cast<const float4*>(cv + 192 + j0);
    float4 bi = *reinterpret_cast<const float4*>(bias + j0);
    float4 bf = *reinterpret_cast<const float4*>(bias + 64 + j0);
    float4 bo = *reinterpret_cast<const float4*>(bias + 128 + j0);
    float4 bg = *reinterpret_cast<const float4*>(bias + 192 + j0);
    float4 cp = *reinterpret_cast<const float4*>(c_cur + (size_t)bn * HID + j0);

    float4 hn, cn;
    {
        float iv = 1.f / (1.f + __expf(-(xi.x + bi.x)));
        float fv = 1.f / (1.f + __expf(-(xf.x + bf.x)));
        float ov = 1.f / (1.f + __expf(-(xo.x + bo.x)));
        float gv = tanhf(xg.x + bg.x);
        cn.x = fmaf(fv, cp.x, iv * gv); hn.x = ov * tanhf(cn.x);
    }
    {
        float iv = 1.f / (1.f + __expf(-(xi.y + bi.y)));
        float fv = 1.f / (1.f + __expf(-(xf.y + bf.y)));
        float ov = 1.f / (1.f + __expf(-(xo.y + bo.y)));
        float gv = tanhf(xg.y + bg.y);
        cn.y = fmaf(fv, cp.y, iv * gv); hn.y = ov * tanhf(cn.y);
    }
    {
        float iv = 1.f / (1.f + __expf(-(xi.z + bi.z)));
        float fv = 1.f / (1.f + __expf(-(xf.z + bf.z)));
        float ov = 1.f / (1.f + __expf(-(xo.z + bo.z)));
        float gv = tanhf(xg.z + bg.z);
        cn.z = fmaf(fv, cp.z, iv * gv); hn.z = ov * tanhf(cn.z);
    }
    {
        float iv = 1.f / (1.f + __expf(-(xi.w + bi.w)));
        float fv = 1.f / (1.f + __expf(-(xf.w + bf.w)));
        float ov = 1.f / (1.f + __expf(-(xo.w + bo.w)));
        float gv = tanhf(xg.w + bg.w);
        cn.w = fmaf(fv, cp.w, iv * gv); hn.w = ov * tanhf(cn.w);
    }
    *reinterpret_cast<float4*>(out + (size_t)bn * HID + j0) = hn;
    *reinterpret_cast<float4*>(out + (size_t)BB * NN * HID + (size_t)bn * HID + j0) = cn;
}

// ---------------------------------------------------------------------------
extern "C" void kernel_launch(void* const* d_in, const int* in_sizes, int n_in,
                              void* d_out, int out_size) {
    const float* inp   = (const float*)d_in[0];
    const float* hcur  = (const float*)d_in[1];
    const float* ccur  = (const float*)d_in[2];
    const float* W     = (const float*)d_in[3];
    const float* att_s = (const float*)d_in[4];
    const float* att_d = (const float*)d_in[5];
    const float* bias  = (const float*)d_in[6];
    const void*  edges = d_in[7];
    float* out = (float*)d_out;

    int E = in_sizes[7] / 2;

    initvs_k<<<81, 256>>>(W, att_s, att_d, (const int*)edges, in_sizes[7]);
    asd_k<<<(BB * NN * 32 + 255) / 256, 256>>>(inp, hcur);
    hist_k<<<(E + 255) / 256, 256>>>(edges, E);
    scan_k<<<1, 1024>>>();
    fill_k<<<(E + 255) / 256, 256>>>(edges, E);
    agg_k<<<(NN * 32 + 255) / 256, 256>>>(inp, hcur);
    gemm_k<<<dim3((NN + 127) / 128, CC / 128, BB), 256>>>(W);
    lstm_k<<<(BB * NN * 16 + 255) / 256, 256>>>(bias, ccur, out);
}